// round 8
// baseline (speedup 1.0000x reference)
#include <cuda_runtime.h>
#include <cuda_bf16.h>
#include <math.h>

#define B 16
#define C 64
#define H 256
#define W 256
#define HW (H*W)        // 65536
#define WG 8            // w per CTA
#define NW 8            // warps per CTA
#define HPW (H/NW)      // 32 h per warp

// CTA = (b, 8-w tile), 256 threads = 8 warps; warp wp owns h in [wp*32, wp*32+32)
// with ZERO mainloop barriers:
//   lane = c3*2 + wq (c3=0..15 channel-group, wq=0..1 float4-of-w)
//   loads: float4 (4 w) for channels c = c3 + 16j, j=0..3  -> 32B/sector exact
//   channel-L2 reduce = 4 in-warp shfl_xor (lane bits 1..4)
//   acc[c][w], sum(e) register-resident. One barrier: combine 8 warp partials.
// Softmax without max-subtraction (args <= ~14 for N(0,1); the shift cancels
// algebraically in weighted_sum/weight_sum).
__global__ __launch_bounds__(256, 4) void fused_kernel(const float* __restrict__ x,
                                                       float* __restrict__ out) {
    __shared__ float4 red[NW][4][32];    // [warp][j][lane] acc partials (16 KB)
    __shared__ float4 ssred[NW][2];      // [warp][wq] sum-e partials
    __shared__ float4 comp_s[C][2];      // compressed[c][wq] (2 KB)

    const int b    = blockIdx.y;
    const int w0   = blockIdx.x * WG;
    const int tid  = threadIdx.x;
    const int lane = tid & 31;
    const int wp   = tid >> 5;        // warp 0..7 -> h slice
    const int c3   = lane >> 1;       // 0..15 channel-group
    const int wq   = lane & 1;        // 0..1 float4-group of w

    const float* xb = x + (size_t)b * C * HW + w0 + wq * 4;

    float4 acc[4];
#pragma unroll
    for (int j = 0; j < 4; j++) acc[j] = make_float4(0.f, 0.f, 0.f, 0.f);
    float4 ssum = make_float4(0.f, 0.f, 0.f, 0.f);

    const int h0 = wp * HPW;
    for (int hi = 0; hi < HPW; hi++) {
        const float* ph = xb + (size_t)(h0 + hi) * W;
        float4 v[4];
#pragma unroll
        for (int j = 0; j < 4; j++)
            v[j] = __ldcs((const float4*)(ph + ((size_t)(c3 + 16 * j) << 16)));

        // partial squared norm over this lane's 4 channels (per w component)
        float4 sq = make_float4(0.f, 0.f, 0.f, 0.f);
#pragma unroll
        for (int j = 0; j < 4; j++) {
            sq.x = fmaf(v[j].x, v[j].x, sq.x);
            sq.y = fmaf(v[j].y, v[j].y, sq.y);
            sq.z = fmaf(v[j].z, v[j].z, sq.z);
            sq.w = fmaf(v[j].w, v[j].w, sq.w);
        }
        // reduce across c3 (lane bits 1..4): masks 2,4,8,16
#pragma unroll
        for (int m = 2; m <= 16; m <<= 1) {
            sq.x += __shfl_xor_sync(0xffffffffu, sq.x, m);
            sq.y += __shfl_xor_sync(0xffffffffu, sq.y, m);
            sq.z += __shfl_xor_sync(0xffffffffu, sq.z, m);
            sq.w += __shfl_xor_sync(0xffffffffu, sq.w, m);
        }
        float4 e;
        e.x = __expf(sqrtf(sq.x));
        e.y = __expf(sqrtf(sq.y));
        e.z = __expf(sqrtf(sq.z));
        e.w = __expf(sqrtf(sq.w));

#pragma unroll
        for (int j = 0; j < 4; j++) {
            acc[j].x = fmaf(v[j].x, e.x, acc[j].x);
            acc[j].y = fmaf(v[j].y, e.y, acc[j].y);
            acc[j].z = fmaf(v[j].z, e.z, acc[j].z);
            acc[j].w = fmaf(v[j].w, e.w, acc[j].w);
        }
        ssum.x += e.x; ssum.y += e.y; ssum.z += e.z; ssum.w += e.w;
    }

    // ---- dump warp partials (lane-consecutive float4: conflict-free)
#pragma unroll
    for (int j = 0; j < 4; j++) red[wp][j][lane] = acc[j];
    if (c3 == 0) ssred[wp][wq] = ssum;
    __syncthreads();

    // ---- combine: thread t<128 handles (c = t>>1, q = t&1)
    if (tid < C * 2) {
        const int c = tid >> 1, q = tid & 1;
        float4 tot = make_float4(0.f, 0.f, 0.f, 0.f);
        float4 st  = make_float4(0.f, 0.f, 0.f, 0.f);
#pragma unroll
        for (int p = 0; p < NW; p++) {
            float4 a = red[p][c >> 4][(c & 15) * 2 + q];
            tot.x += a.x; tot.y += a.y; tot.z += a.z; tot.w += a.w;
            float4 s = ssred[p][q];
            st.x += s.x; st.y += s.y; st.z += s.z; st.w += s.w;
        }
        float4 o;
        o.x = tot.x / (st.x * (1.0f + 1e-8f));
        o.y = tot.y / (st.y * (1.0f + 1e-8f));
        o.z = tot.z / (st.z * (1.0f + 1e-8f));
        o.w = tot.w / (st.w * (1.0f + 1e-8f));
        comp_s[c][q] = o;
    }
    __syncthreads();

    // ---- broadcast-write over h: thread = (hh = tid>>1: 0..127, q = tid&1)
    const int q  = tid & 1;
    const int hh = tid >> 1;
    float* ob = out + (size_t)b * C * HW + w0 + q * 4 + (size_t)hh * W;
#pragma unroll 1
    for (int c = 0; c < C; c++) {
        float4 val = comp_s[c][q];
        float* oc = ob + ((size_t)c << 16);
        __stcs((float4*)oc, val);
        __stcs((float4*)(oc + (size_t)128 * W), val);
    }
}

extern "C" void kernel_launch(void* const* d_in, const int* in_sizes, int n_in,
                              void* d_out, int out_size) {
    const float* x = (const float*)d_in[0];
    float* out = (float*)d_out;
    dim3 grid(W / WG, B);
    fused_kernel<<<grid, 256>>>(x, out);
}

// round 10
// speedup vs baseline: 1.3246x; 1.3246x over previous
#include <cuda_runtime.h>
#include <cuda_bf16.h>
#include <math.h>

#define B 16
#define C 64
#define H 256
#define W 256
#define HW (H*W)        // 65536
#define WG 16           // w per task tile
#define NHQ 4           // h quarters
#define HQL 64          // h per quarter
#define NWT (W/WG)      // 16 w tiles

// Scratch partials (no cudaMalloc allowed): ~4.5 MB
__device__ float g_part[B][NWT][NHQ][C * WG];   // [b][wt][hq][c*16+wl]
__device__ float g_ssum[B][NWT][NHQ][WG];       // [b][wt][hq][wl]

// ---------------- Kernel A: partial weighted sums over one h-quarter ----------------
// CTA = (hq, wt, b), 64 threads = 2 warps; warp wp streams h in
// [hq*64 + wp*32, +32) with zero barriers:
//   lane = c3*4 + wq: float4 (4 w) for channels c = c3 + 8j, j=0..7
//   -> 8 lines x 64B per LDG (the proven-fast memory shape)
//   channel-L2 reduce = 3 in-warp shfl_xor; e = exp(sqrt(.)) in-lane.
// Softmax without max-subtraction (args <= ~14 for N(0,1); the shift cancels
// in weighted_sum/weight_sum). Partials over h are additive -> combined in B.
__global__ __launch_bounds__(64) void partial_kernel(const float* __restrict__ x) {
    __shared__ float4 red[2][8][32];   // [warp][j][lane] acc partials (8 KB)
    __shared__ float4 ssred[2][4];     // [warp][wq] sum-e partials

    const int hq = blockIdx.x;
    const int wt = blockIdx.y;
    const int b  = blockIdx.z;
    const int tid  = threadIdx.x;
    const int lane = tid & 31;
    const int wp   = tid >> 5;        // warp 0..1
    const int c3   = lane >> 2;       // 0..7 channel-group
    const int wq   = lane & 3;        // 0..3 float4-group of w

    const float* xb = x + (size_t)b * C * HW + wt * WG + wq * 4;

    float4 acc[8];
#pragma unroll
    for (int j = 0; j < 8; j++) acc[j] = make_float4(0.f, 0.f, 0.f, 0.f);
    float4 ssum = make_float4(0.f, 0.f, 0.f, 0.f);

    const int h0 = hq * HQL + wp * 32;
    for (int hi = 0; hi < 32; hi++) {
        const float* ph = xb + (size_t)(h0 + hi) * W;
        float4 v[8];
#pragma unroll
        for (int j = 0; j < 8; j++)
            v[j] = __ldcs((const float4*)(ph + ((size_t)(c3 + 8 * j) << 16)));

        float4 sq = make_float4(0.f, 0.f, 0.f, 0.f);
#pragma unroll
        for (int j = 0; j < 8; j++) {
            sq.x = fmaf(v[j].x, v[j].x, sq.x);
            sq.y = fmaf(v[j].y, v[j].y, sq.y);
            sq.z = fmaf(v[j].z, v[j].z, sq.z);
            sq.w = fmaf(v[j].w, v[j].w, sq.w);
        }
        // reduce across c3 (lane bits 2..4): masks 4, 8, 16
#pragma unroll
        for (int m = 4; m <= 16; m <<= 1) {
            sq.x += __shfl_xor_sync(0xffffffffu, sq.x, m);
            sq.y += __shfl_xor_sync(0xffffffffu, sq.y, m);
            sq.z += __shfl_xor_sync(0xffffffffu, sq.z, m);
            sq.w += __shfl_xor_sync(0xffffffffu, sq.w, m);
        }
        float4 e;
        e.x = __expf(sqrtf(sq.x));
        e.y = __expf(sqrtf(sq.y));
        e.z = __expf(sqrtf(sq.z));
        e.w = __expf(sqrtf(sq.w));

#pragma unroll
        for (int j = 0; j < 8; j++) {
            acc[j].x = fmaf(v[j].x, e.x, acc[j].x);
            acc[j].y = fmaf(v[j].y, e.y, acc[j].y);
            acc[j].z = fmaf(v[j].z, e.z, acc[j].z);
            acc[j].w = fmaf(v[j].w, e.w, acc[j].w);
        }
        ssum.x += e.x; ssum.y += e.y; ssum.z += e.z; ssum.w += e.w;
    }

#pragma unroll
    for (int j = 0; j < 8; j++) red[wp][j][lane] = acc[j];
    if (c3 == 0) ssred[wp][wq] = ssum;
    __syncthreads();

    // combine the 2 warps, dump partials to scratch (float4, coalesced)
    float4* gp = (float4*)g_part[b][wt][hq];
#pragma unroll
    for (int idx = tid; idx < C * 4; idx += 64) {
        const int c = idx >> 2, q = idx & 3;
        float4 a0 = red[0][c >> 3][(c & 7) * 4 + q];
        float4 a1 = red[1][c >> 3][(c & 7) * 4 + q];
        a0.x += a1.x; a0.y += a1.y; a0.z += a1.z; a0.w += a1.w;
        gp[idx] = a0;
    }
    if (tid < 4) {
        float4 s0 = ssred[0][tid], s1 = ssred[1][tid];
        s0.x += s1.x; s0.y += s1.y; s0.z += s1.z; s0.w += s1.w;
        ((float4*)g_ssum[b][wt][hq])[tid] = s0;
    }
}

// ---------------- Kernel B: combine partials + broadcast-write ----------------
// CTA = (hh, c, b), 128 threads. Computes comp[w] for its (b,c) from the 4
// h-quarter partials (scratch is L2-resident: read 64x each), then streams
// 128 h-rows of float4 stores (perfectly coalesced, 512B/warp/row).
__global__ __launch_bounds__(128) void write_kernel(float* __restrict__ out) {
    __shared__ float comp[W];

    const int hh = blockIdx.x;     // 0..1 (h half)
    const int c  = blockIdx.y;     // 0..63
    const int b  = blockIdx.z;     // 0..15
    const int tid = threadIdx.x;

    for (int w = tid; w < W; w += 128) {
        const int wt = w >> 4, wl = w & 15;
        float tot = 0.f, ss = 0.f;
#pragma unroll
        for (int hq = 0; hq < NHQ; hq++) {
            tot += g_part[b][wt][hq][c * WG + wl];
            ss  += g_ssum[b][wt][hq][wl];
        }
        comp[w] = tot / (ss * (1.0f + 1e-8f));
    }
    __syncthreads();

    float* ob = out + ((size_t)b * C + c) * HW + (size_t)hh * 128 * W;
    const float4* c4 = (const float4*)comp;
    const int q  = tid & 63;        // float4 index within the w row
    const int h0 = tid >> 6;        // 0..1
    const float4 val = c4[q];
#pragma unroll 4
    for (int h = h0; h < 128; h += 2)
        __stcs(((float4*)(ob + (size_t)h * W)) + q, val);
}

extern "C" void kernel_launch(void* const* d_in, const int* in_sizes, int n_in,
                              void* d_out, int out_size) {
    const float* x = (const float*)d_in[0];
    float* out = (float*)d_out;

    dim3 gridA(NHQ, NWT, B);
    partial_kernel<<<gridA, 64>>>(x);

    dim3 gridB(2, C, B);
    write_kernel<<<gridB, 128>>>(out);
}

// round 11
// speedup vs baseline: 1.3524x; 1.0211x over previous
#include <cuda_runtime.h>
#include <cuda_bf16.h>
#include <math.h>

#define B 16
#define C 64
#define H 256
#define W 256
#define HW (H*W)        // 65536
#define WG 16           // w per task tile
#define NHQ 4           // h quarters
#define HQL 64          // h per quarter
#define NWT (W/WG)      // 16 w tiles

// Scratch partials (no cudaMalloc allowed): ~4.5 MB
__device__ float g_part[B][NWT][NHQ][C * WG];   // [b][wt][hq][c*16+wl]
__device__ float g_ssum[B][NWT][NHQ][WG];       // [b][wt][hq][wl]

// ---------------- Kernel A: partial weighted sums over one h-quarter ----------------
// CTA = (hq, wt, b), 64 threads = 2 warps; warp wp streams 32 h's, barriers-free.
//   lane = c3*4 + wq: float4 (4 w) for channels c = c3 + 8j, j=0..7 (8x64B lines)
//   IN-WARP DOUBLE BUFFER: prefetch h+1's 8 loads before processing h
//   -> 16 lines in flight/warp; 14 warps/SM * 16 * 128B/577cyc ~ 50 B/cyc > 42 needed.
// Softmax without max-subtraction (args <= ~14 for N(0,1); shift cancels in
// weighted_sum/weight_sum). h-partials are additive -> combined in kernel B.
__global__ __launch_bounds__(64, 8) void partial_kernel(const float* __restrict__ x) {
    __shared__ float4 red[2][8][32];   // [warp][j][lane] acc partials (8 KB)
    __shared__ float4 ssred[2][4];     // [warp][wq] sum-e partials

    const int hq = blockIdx.x;
    const int wt = blockIdx.y;
    const int b  = blockIdx.z;
    const int tid  = threadIdx.x;
    const int lane = tid & 31;
    const int wp   = tid >> 5;        // warp 0..1
    const int c3   = lane >> 2;       // 0..7 channel-group
    const int wq   = lane & 3;        // 0..3 float4-group of w

    const float* xb = x + (size_t)b * C * HW + wt * WG + wq * 4
                        + ((size_t)c3 << 16)
                        + (size_t)(hq * HQL + wp * 32) * W;

    float4 acc[8];
#pragma unroll
    for (int j = 0; j < 8; j++) acc[j] = make_float4(0.f, 0.f, 0.f, 0.f);
    float4 ssum = make_float4(0.f, 0.f, 0.f, 0.f);

    float4 v[2][8];
#pragma unroll
    for (int j = 0; j < 8; j++)
        v[0][j] = __ldcs((const float4*)(xb + ((size_t)(8 * j) << 16)));

#pragma unroll 2
    for (int hi = 0; hi < 32; hi++) {
        const int cur = hi & 1;
        // prefetch h+1 (loads in flight across this iteration's shfl/exp chain)
        if (hi < 31) {
            const float* pn = xb + (size_t)(hi + 1) * W;
#pragma unroll
            for (int j = 0; j < 8; j++)
                v[cur ^ 1][j] = __ldcs((const float4*)(pn + ((size_t)(8 * j) << 16)));
        }

        float4 sq = make_float4(0.f, 0.f, 0.f, 0.f);
#pragma unroll
        for (int j = 0; j < 8; j++) {
            sq.x = fmaf(v[cur][j].x, v[cur][j].x, sq.x);
            sq.y = fmaf(v[cur][j].y, v[cur][j].y, sq.y);
            sq.z = fmaf(v[cur][j].z, v[cur][j].z, sq.z);
            sq.w = fmaf(v[cur][j].w, v[cur][j].w, sq.w);
        }
        // reduce across c3 (lane bits 2..4)
#pragma unroll
        for (int m = 4; m <= 16; m <<= 1) {
            sq.x += __shfl_xor_sync(0xffffffffu, sq.x, m);
            sq.y += __shfl_xor_sync(0xffffffffu, sq.y, m);
            sq.z += __shfl_xor_sync(0xffffffffu, sq.z, m);
            sq.w += __shfl_xor_sync(0xffffffffu, sq.w, m);
        }
        float4 e;
        e.x = __expf(sqrtf(sq.x));
        e.y = __expf(sqrtf(sq.y));
        e.z = __expf(sqrtf(sq.z));
        e.w = __expf(sqrtf(sq.w));

#pragma unroll
        for (int j = 0; j < 8; j++) {
            acc[j].x = fmaf(v[cur][j].x, e.x, acc[j].x);
            acc[j].y = fmaf(v[cur][j].y, e.y, acc[j].y);
            acc[j].z = fmaf(v[cur][j].z, e.z, acc[j].z);
            acc[j].w = fmaf(v[cur][j].w, e.w, acc[j].w);
        }
        ssum.x += e.x; ssum.y += e.y; ssum.z += e.z; ssum.w += e.w;
    }

#pragma unroll
    for (int j = 0; j < 8; j++) red[wp][j][lane] = acc[j];
    if (c3 == 0) ssred[wp][wq] = ssum;
    __syncthreads();

    // combine the 2 warps, dump partials to scratch (float4, coalesced)
    float4* gp = (float4*)g_part[b][wt][hq];
#pragma unroll
    for (int idx = tid; idx < C * 4; idx += 64) {
        const int c = idx >> 2, q = idx & 3;
        float4 a0 = red[0][c >> 3][(c & 7) * 4 + q];
        float4 a1 = red[1][c >> 3][(c & 7) * 4 + q];
        a0.x += a1.x; a0.y += a1.y; a0.z += a1.z; a0.w += a1.w;
        gp[idx] = a0;
    }
    if (tid < 4) {
        float4 s0 = ssred[0][tid], s1 = ssred[1][tid];
        s0.x += s1.x; s0.y += s1.y; s0.z += s1.z; s0.w += s1.w;
        ((float4*)g_ssum[b][wt][hq])[tid] = s0;
    }
}

// ---------------- Kernel B: combine partials + broadcast-write ----------------
// CTA = (c, b): one full [H,W] output plane per CTA (256 KB). 1024 CTAs of 256
// threads -> single wave {7:136, 6:12} = ~99% balance. Partial reads are
// L2-resident (each read 64x across c).
__global__ __launch_bounds__(256) void write_kernel(float* __restrict__ out) {
    __shared__ float comp[W];

    const int c  = blockIdx.x;     // 0..63
    const int b  = blockIdx.y;     // 0..15
    const int tid = threadIdx.x;

    {   // combine: thread = w
        const int wt = tid >> 4, wl = tid & 15;
        float tot = 0.f, ss = 0.f;
#pragma unroll
        for (int hq = 0; hq < NHQ; hq++) {
            tot += g_part[b][wt][hq][c * WG + wl];
            ss  += g_ssum[b][wt][hq][wl];
        }
        comp[tid] = tot / (ss * (1.0f + 1e-8f));
    }
    __syncthreads();

    float* ob = out + ((size_t)b * C + c) * HW;
    const float4* c4 = (const float4*)comp;
    const int q  = tid & 63;        // float4 index within the w row
    const int h0 = tid >> 6;        // 0..3
    const float4 val = c4[q];
#pragma unroll 8
    for (int h = h0; h < H; h += 4)
        __stcs(((float4*)(ob + (size_t)h * W)) + q, val);
}

extern "C" void kernel_launch(void* const* d_in, const int* in_sizes, int n_in,
                              void* d_out, int out_size) {
    const float* x = (const float*)d_in[0];
    float* out = (float*)d_out;

    dim3 gridA(NHQ, NWT, B);
    partial_kernel<<<gridA, 64>>>(x);

    dim3 gridB(C, B);
    write_kernel<<<gridB, 256>>>(out);
}